// round 11
// baseline (speedup 1.0000x reference)
#include <cuda_runtime.h>
#include <cuda_bf16.h>
#include <math.h>
#include <stdint.h>

#define BB   2
#define SQL  2048
#define DM   1024
#define NH   16
#define DH   64
#define BH   32
#define ROWS 4096

typedef __nv_bfloat16 bf16;

// ---------------- scratch (__device__ globals) -----------------------------
__device__ bf16 g_Qh[BH * SQL * DH];
__device__ bf16 g_Ql[BH * SQL * DH];
__device__ bf16 g_Kh[BH * SQL * DH];
__device__ bf16 g_Kl[BH * SQL * DH];
__device__ bf16 g_Vh[BH * SQL * DH];
__device__ bf16 g_Vl[BH * SQL * DH];
__device__ bf16 g_Ah[ROWS * DM];   // x1 split; later ctx split
__device__ bf16 g_Al[ROWS * DM];
__device__ bf16 g_Bh[ROWS * DM];   // x2 split
__device__ bf16 g_Bl[ROWS * DM];
__device__ bf16 g_Wqh[DM * DM], g_Wql[DM * DM];   // untransposed [k][n]
__device__ bf16 g_Wkh[DM * DM], g_Wkl[DM * DM];
__device__ bf16 g_Wvh[DM * DM], g_Wvl[DM * DM];
__device__ bf16 g_Woh[DM * DM], g_Wol[DM * DM];

// ---------------- helpers --------------------------------------------------
__device__ __forceinline__ uint32_t smem_to_u32(const void* p) {
    uint32_t a;
    asm("{ .reg .u64 t; cvta.to.shared.u64 t, %1; cvt.u32.u64 %0, t; }"
        : "=r"(a) : "l"(p));
    return a;
}
__device__ __forceinline__ void ldsm4(uint32_t* r, uint32_t a) {
    asm volatile("ldmatrix.sync.aligned.m8n8.x4.shared.b16 {%0,%1,%2,%3}, [%4];"
        : "=r"(r[0]), "=r"(r[1]), "=r"(r[2]), "=r"(r[3]) : "r"(a));
}
__device__ __forceinline__ void ldsm4t(uint32_t* r, uint32_t a) {
    asm volatile("ldmatrix.sync.aligned.m8n8.x4.trans.shared.b16 {%0,%1,%2,%3}, [%4];"
        : "=r"(r[0]), "=r"(r[1]), "=r"(r[2]), "=r"(r[3]) : "r"(a));
}
__device__ __forceinline__ void mma16816(float* c, const uint32_t* a, const uint32_t* b) {
    asm volatile("mma.sync.aligned.m16n8k16.row.col.f32.bf16.bf16.f32 "
        "{%0,%1,%2,%3}, {%4,%5,%6,%7}, {%8,%9}, {%0,%1,%2,%3};"
        : "+f"(c[0]), "+f"(c[1]), "+f"(c[2]), "+f"(c[3])
        : "r"(a[0]), "r"(a[1]), "r"(a[2]), "r"(a[3]), "r"(b[0]), "r"(b[1]));
}
__device__ __forceinline__ void split2(float v0, float v1, uint32_t& hi2, uint32_t& lo2) {
    __nv_bfloat16 b0 = __float2bfloat16_rn(v0), b1 = __float2bfloat16_rn(v1);
    union { __nv_bfloat162 v; uint32_t u; } p;
    p.v.x = b0; p.v.y = b1; hi2 = p.u;
    p.v.x = __float2bfloat16_rn(v0 - __bfloat162float(b0));
    p.v.y = __float2bfloat16_rn(v1 - __bfloat162float(b1));
    lo2 = p.u;
}
__device__ __forceinline__ float ex2(float x) {
    float y; asm("ex2.approx.f32 %0, %1;" : "=f"(y) : "f"(x)); return y;
}
#define CP16(dst, src) \
    asm volatile("cp.async.cg.shared.global [%0], [%1], 16;" :: "r"(dst), "l"(src))
#define CP_COMMIT() asm volatile("cp.async.commit_group;" ::: "memory")
#define CP_WAIT(n)  asm volatile("cp.async.wait_group %0;" :: "n"(n) : "memory")

// ---------------- one split kernel for x1, x2, and the 4 weights -----------
struct SArgs { const float* s[6]; bf16* h[6]; bf16* l[6]; };
__global__ __launch_bounds__(256)
void convS_kernel(SArgs a)
{
    int bi = blockIdx.x, z;
    if (bi < 4096)       { z = 0; }
    else if (bi < 8192)  { z = 1; bi -= 4096; }
    else                 { z = 2 + ((bi - 8192) >> 10); bi = (bi - 8192) & 1023; }
    const float* __restrict__ x = a.s[z];
    bf16* __restrict__ hi = a.h[z];
    bf16* __restrict__ lo = a.l[z];
    int i = bi * 256 + threadIdx.x;
    float4 v = ((const float4*)x)[i];
    uint32_t h0, l0, h1, l1;
    split2(v.x, v.y, h0, l0);
    split2(v.z, v.w, h1, l1);
    ((uint32_t*)hi)[2 * i] = h0; ((uint32_t*)hi)[2 * i + 1] = h1;
    ((uint32_t*)lo)[2 * i] = l0; ((uint32_t*)lo)[2 * i + 1] = l1;
}

// ---------------- split-bf16 GEMM: 64x128 tile, 128 thr, 2 CTA/SM, 4-stage -
// C[m][n] = sum_k (Ah+Al)[m][k] * (Wh+Wl)[k][n]  (W untransposed; B via ldsm4t)
// stage: Ah 64x80B, Al 64x80B, Bh 32x256B, Bl 32x256B = 26624 B; 4 stages.
struct GArgs {
    const bf16* Ah[3]; const bf16* Al[3];
    const bf16* Wh[3]; const bf16* Wl[3];
    const float* bias[3];
    bf16* oh[3]; bf16* ol[3];
    float* of[3];
    float scale[3];
};
#define GSTG   26624
#define G_OFAL 5120
#define G_OFBH 10240
__global__ __launch_bounds__(128, 2)
void gemm_mma(GArgs ar)
{
    extern __shared__ __align__(16) char dsm[];
    const int z = blockIdx.z;
    const bf16* __restrict__ Ah = ar.Ah[z];
    const bf16* __restrict__ Al = ar.Al[z];
    const bf16* __restrict__ Wh = ar.Wh[z];
    const bf16* __restrict__ Wl = ar.Wl[z];
    const float* __restrict__ bias = ar.bias[z];
    const float scale = ar.scale[z];

    const uint32_t sb0 = smem_to_u32(dsm);
    const int t = threadIdx.x, L = t & 31, wid = t >> 5;
    const int wm = wid & 1, wn = wid >> 1;          // 2x2 warp grid
    const int m0 = blockIdx.y * 64, n0 = blockIdx.x * 128;

    auto copy_stage = [&](int st, int k0) {
        const uint32_t base = sb0 + st * GSTG;
#pragma unroll
        for (int i = 0; i < 2; i++) {
            const int u = t + i * 128, r = u >> 2, c = u & 3;
            const uint32_t d = base + r * 80 + c * 16;
            const size_t gi = (size_t)(m0 + r) * DM + k0 + c * 8;
            CP16(d,          Ah + gi);
            CP16(d + G_OFAL, Al + gi);
        }
#pragma unroll
        for (int i = 0; i < 4; i++) {
            const int u = t + i * 128, r = u >> 4, c = u & 15;
            const uint32_t d = base + G_OFBH + r * 256 + (c ^ (r & 7)) * 16;
            const size_t gi = (size_t)(k0 + r) * DM + n0 + c * 8;
            CP16(d,        Wh + gi);
            CP16(d + 8192, Wl + gi);
        }
    };

    float acc[2][8][4];
#pragma unroll
    for (int a = 0; a < 2; a++)
#pragma unroll
        for (int b = 0; b < 8; b++)
#pragma unroll
            for (int c = 0; c < 4; c++) acc[a][b][c] = 0.0f;

    const int a_row_off = ((L >> 3) & 1) * 8 + (L & 7);
    const int a_ch = (L >> 4);
    const int trow = ((L >> 3) & 1) * 8 + (L & 7);   // B trans row pattern
    const int tcb  = (L >> 4);                       // B trans chunk half
    const int sw7  = L & 7;

    copy_stage(0, 0);  CP_COMMIT();
    copy_stage(1, 32); CP_COMMIT();
    copy_stage(2, 64); CP_COMMIT();

    for (int kt = 0; kt < 32; kt++) {
        // ensure stage kt landed; allow 2 newer copies in flight
        if (kt <= 29)      CP_WAIT(2);
        else if (kt == 30) CP_WAIT(1);
        else               CP_WAIT(0);
        __syncthreads();
        if (kt < 29) { copy_stage((kt + 3) & 3, (kt + 3) * 32); CP_COMMIT(); }
        const uint32_t sb = sb0 + (kt & 3) * GSTG;
#pragma unroll
        for (int ks = 0; ks < 2; ks++) {
            uint32_t aH[2][4], aL[2][4];
            const int ach = (2 * ks + a_ch) * 16;
#pragma unroll
            for (int mt = 0; mt < 2; mt++) {
                const uint32_t ad = sb + (wm * 32 + mt * 16 + a_row_off) * 80 + ach;
                ldsm4(aH[mt], ad);
                ldsm4(aL[mt], ad + G_OFAL);
            }
            const int krow = ks * 16 + trow;
#pragma unroll
            for (int ns = 0; ns < 4; ns++) {
                uint32_t bTh[4], bTl[4];
                const int ch = 2 * (wn * 4 + ns) + tcb;
                const uint32_t bd = sb + G_OFBH + krow * 256 + ((ch ^ sw7) << 4);
                ldsm4t(bTh, bd);
                ldsm4t(bTl, bd + 8192);
#pragma unroll
                for (int mt = 0; mt < 2; mt++) {
                    mma16816(acc[mt][2 * ns],     aH[mt], &bTh[0]);
                    mma16816(acc[mt][2 * ns],     aH[mt], &bTl[0]);
                    mma16816(acc[mt][2 * ns],     aL[mt], &bTh[0]);
                    mma16816(acc[mt][2 * ns + 1], aH[mt], &bTh[2]);
                    mma16816(acc[mt][2 * ns + 1], aH[mt], &bTl[2]);
                    mma16816(acc[mt][2 * ns + 1], aL[mt], &bTh[2]);
                }
            }
        }
    }

    bf16* __restrict__ outH = ar.oh[z];
    bf16* __restrict__ outL = ar.ol[z];
    float* __restrict__ outF = ar.of[z];
    const int g = L >> 2, tg = L & 3;
#pragma unroll
    for (int mt = 0; mt < 2; mt++) {
#pragma unroll
        for (int nt = 0; nt < 8; nt++) {
            const int mrow = m0 + wm * 32 + mt * 16 + g;
            const int ncol = n0 + wn * 64 + nt * 8 + 2 * tg;
            const float b0v = bias[ncol], b1v = bias[ncol + 1];
            const float v00 = (acc[mt][nt][0] + b0v) * scale;
            const float v01 = (acc[mt][nt][1] + b1v) * scale;
            const float v10 = (acc[mt][nt][2] + b0v) * scale;
            const float v11 = (acc[mt][nt][3] + b1v) * scale;
            if (outF) {
                *(float2*)(outF + (size_t)mrow * DM + ncol) = make_float2(v00, v01);
                *(float2*)(outF + (size_t)(mrow + 8) * DM + ncol) = make_float2(v10, v11);
            } else {
                const int b_ = mrow >> 11, s_ = mrow & 2047;
                const int h_ = ncol >> 6, d_ = ncol & 63;
                const size_t oi = ((size_t)(b_ * NH + h_) * SQL + s_) * DH + d_;
                uint32_t h2, l2;
                split2(v00, v01, h2, l2);
                *(uint32_t*)(outH + oi) = h2;
                *(uint32_t*)(outL + oi) = l2;
                split2(v10, v11, h2, l2);
                *(uint32_t*)(outH + oi + 8 * DH) = h2;
                *(uint32_t*)(outL + oi + 8 * DH) = l2;
            }
        }
    }
}

// ---------------- flash attention (unchanged: 245us, tensor 69%) -----------
#define A_SMEM  81920
#define ASTG_B  16384
#define ASTG_S  32768
__global__ __launch_bounds__(128, 2)
void attn_mma(const bf16* __restrict__ Qh, const bf16* __restrict__ Ql,
              const bf16* __restrict__ Kh, const bf16* __restrict__ Kl,
              const bf16* __restrict__ Vh, const bf16* __restrict__ Vl,
              bf16* __restrict__ Ch, bf16* __restrict__ Cl)
{
    extern __shared__ __align__(16) char sm_[];
    const uint32_t sb = smem_to_u32(sm_);
    const int t = threadIdx.x, L = t & 31, wid = t >> 5;
    const int bh = blockIdx.y, q0 = blockIdx.x * 64;
    const int g = L >> 2, tg = L & 3;

    const int a_row = wid * 16 + ((L >> 3) & 1) * 8 + (L & 7);
    const int a_cb  = (L >> 4);
    const int k_row_off = ((L >> 4) & 1) * 8 + (L & 7);
    const int k_cb  = ((L >> 3) & 1);
    const int v_row_off = ((L >> 3) & 1) * 8 + (L & 7);
    const int v_cb  = (L >> 4);
    const int sw    = L & 7;

    auto copy_kv = [&](int st, int kb) {
        const uint32_t base = sb + ASTG_B + st * ASTG_S;
        const size_t goff = ((size_t)bh * SQL + kb * 64) * DH;
        const char* kh = (const char*)(Kh + goff);
        const char* kl = (const char*)(Kl + goff);
        const char* vh = (const char*)(Vh + goff);
        const char* vl = (const char*)(Vl + goff);
#pragma unroll
        for (int i = 0; i < 4; i++) {
            const int u = t + i * 128, r = u >> 3, c = u & 7;
            const uint32_t so = r * 128 + ((c ^ (r & 7)) << 4);
            const int go = r * 128 + c * 16;
            CP16(base + so,         kh + go);
            CP16(base + 8192 + so,  kl + go);
            CP16(base + 16384 + so, vh + go);
            CP16(base + 24576 + so, vl + go);
        }
    };

    copy_kv(0, 0);
    {
        const char* qh = (const char*)(Qh + ((size_t)bh * SQL + q0) * DH);
        const char* ql = (const char*)(Ql + ((size_t)bh * SQL + q0) * DH);
#pragma unroll
        for (int i = 0; i < 4; i++) {
            const int u = t + i * 128, r = u >> 3, c = u & 7;
            const uint32_t so = r * 128 + ((c ^ (r & 7)) << 4);
            const int go = r * 128 + c * 16;
            CP16(sb + so,        qh + go);
            CP16(sb + 8192 + so, ql + go);
        }
    }
    CP_COMMIT();
    CP_WAIT(0);
    __syncthreads();

    uint32_t qH[4][4], qL[4][4];
#pragma unroll
    for (int ks = 0; ks < 4; ks++) {
        const uint32_t qa = sb + a_row * 128 + (((2 * ks + a_cb) ^ sw) << 4);
        ldsm4(qH[ks], qa);
        ldsm4(qL[ks], qa + 8192);
    }

    float oacc[8][4];
#pragma unroll
    for (int a = 0; a < 8; a++)
#pragma unroll
        for (int b = 0; b < 4; b++) oacc[a][b] = 0.0f;
    float m0r = -1e30f, m1r = -1e30f, l0r = 0.0f, l1r = 0.0f;

    for (int kb = 0; kb < 32; kb++) {
        const int cur = kb & 1;
        if (kb < 31) { copy_kv(1 - cur, kb + 1); CP_COMMIT(); CP_WAIT(1); }
        else CP_WAIT(0);
        __syncthreads();
        const uint32_t kbase = sb + ASTG_B + cur * ASTG_S;

        float sacc[8][4];
#pragma unroll
        for (int j = 0; j < 8; j++)
#pragma unroll
            for (int c = 0; c < 4; c++) sacc[j][c] = 0.0f;

#pragma unroll
        for (int ks = 0; ks < 4; ks++) {
#pragma unroll
            for (int jp = 0; jp < 4; jp++) {
                uint32_t kh4[4], kl4[4];
                const int krow = jp * 16 + k_row_off;
                const uint32_t ka = kbase + krow * 128 + (((2 * ks + k_cb) ^ sw) << 4);
                ldsm4(kh4, ka);
                ldsm4(kl4, ka + 8192);
                mma16816(sacc[2 * jp],     qH[ks], &kh4[0]);
                mma16816(sacc[2 * jp],     qH[ks], &kl4[0]);
                mma16816(sacc[2 * jp],     qL[ks], &kh4[0]);
                mma16816(sacc[2 * jp + 1], qH[ks], &kh4[2]);
                mma16816(sacc[2 * jp + 1], qH[ks], &kl4[2]);
                mma16816(sacc[2 * jp + 1], qL[ks], &kh4[2]);
            }
        }

        float rx0 = -1e30f, rx1 = -1e30f;
#pragma unroll
        for (int j = 0; j < 8; j++) {
            rx0 = fmaxf(rx0, fmaxf(sacc[j][0], sacc[j][1]));
            rx1 = fmaxf(rx1, fmaxf(sacc[j][2], sacc[j][3]));
        }
        rx0 = fmaxf(rx0, __shfl_xor_sync(0xffffffffu, rx0, 1));
        rx0 = fmaxf(rx0, __shfl_xor_sync(0xffffffffu, rx0, 2));
        rx1 = fmaxf(rx1, __shfl_xor_sync(0xffffffffu, rx1, 1));
        rx1 = fmaxf(rx1, __shfl_xor_sync(0xffffffffu, rx1, 2));
        const float mn0 = fmaxf(m0r, rx0), mn1 = fmaxf(m1r, rx1);
        const float al0 = ex2(m0r - mn0), al1 = ex2(m1r - mn1);
        m0r = mn0; m1r = mn1;

        float rs0 = 0.0f, rs1 = 0.0f;
#pragma unroll
        for (int j = 0; j < 8; j++) {
            const float p0 = ex2(sacc[j][0] - mn0);
            const float p1 = ex2(sacc[j][1] - mn0);
            const float p2 = ex2(sacc[j][2] - mn1);
            const float p3 = ex2(sacc[j][3] - mn1);
            sacc[j][0] = p0; sacc[j][1] = p1; sacc[j][2] = p2; sacc[j][3] = p3;
            rs0 += p0 + p1; rs1 += p2 + p3;
        }
        rs0 += __shfl_xor_sync(0xffffffffu, rs0, 1);
        rs0 += __shfl_xor_sync(0xffffffffu, rs0, 2);
        rs1 += __shfl_xor_sync(0xffffffffu, rs1, 1);
        rs1 += __shfl_xor_sync(0xffffffffu, rs1, 2);
        l0r = l0r * al0 + rs0;
        l1r = l1r * al1 + rs1;
#pragma unroll
        for (int jd = 0; jd < 8; jd++) {
            oacc[jd][0] *= al0; oacc[jd][1] *= al0;
            oacc[jd][2] *= al1; oacc[jd][3] *= al1;
        }

#pragma unroll
        for (int ks2 = 0; ks2 < 4; ks2++) {
            uint32_t ph[4], pl[4];
            split2(sacc[2 * ks2][0],     sacc[2 * ks2][1],     ph[0], pl[0]);
            split2(sacc[2 * ks2][2],     sacc[2 * ks2][3],     ph[1], pl[1]);
            split2(sacc[2 * ks2 + 1][0], sacc[2 * ks2 + 1][1], ph[2], pl[2]);
            split2(sacc[2 * ks2 + 1][2], sacc[2 * ks2 + 1][3], ph[3], pl[3]);
#pragma unroll
            for (int jdp = 0; jdp < 4; jdp++) {
                uint32_t vh4[4], vl4[4];
                const int vrow = ks2 * 16 + v_row_off;
                const uint32_t va = kbase + 16384 + vrow * 128
                                  + (((2 * jdp + v_cb) ^ sw) << 4);
                ldsm4t(vh4, va);
                ldsm4t(vl4, va + 8192);
                mma16816(oacc[2 * jdp],     ph, &vh4[0]);
                mma16816(oacc[2 * jdp],     ph, &vl4[0]);
                mma16816(oacc[2 * jdp],     pl, &vh4[0]);
                mma16816(oacc[2 * jdp + 1], ph, &vh4[2]);
                mma16816(oacc[2 * jdp + 1], ph, &vl4[2]);
                mma16816(oacc[2 * jdp + 1], pl, &vh4[2]);
            }
        }
        __syncthreads();
    }

    const float inv0 = 1.0f / l0r, inv1 = 1.0f / l1r;
    const int b_ = bh >> 4, h_ = bh & 15;
    const int q_g = q0 + wid * 16 + g;
    const size_t base0 = ((size_t)(b_ * SQL + q_g)) * DM + h_ * DH;
    const size_t base1 = base0 + (size_t)8 * DM;
#pragma unroll
    for (int jd = 0; jd < 8; jd++) {
        const int dcol = jd * 8 + 2 * tg;
        uint32_t h2, l2;
        split2(oacc[jd][0] * inv0, oacc[jd][1] * inv0, h2, l2);
        *(uint32_t*)(Ch + base0 + dcol) = h2;
        *(uint32_t*)(Cl + base0 + dcol) = l2;
        split2(oacc[jd][2] * inv1, oacc[jd][3] * inv1, h2, l2);
        *(uint32_t*)(Ch + base1 + dcol) = h2;
        *(uint32_t*)(Cl + base1 + dcol) = l2;
    }
}

// ---------------------------------------------------------------------------
extern "C" void kernel_launch(void* const* d_in, const int* in_sizes, int n_in,
                              void* d_out, int out_size)
{
    const float* x1 = (const float*)d_in[0];
    const float* x2 = (const float*)d_in[1];
    const float* Wq = (const float*)d_in[2];
    const float* bq = (const float*)d_in[3];
    const float* Wk = (const float*)d_in[4];
    const float* bk = (const float*)d_in[5];
    const float* Wv = (const float*)d_in[6];
    const float* bv = (const float*)d_in[7];
    const float* Wo = (const float*)d_in[8];
    const float* bo = (const float*)d_in[9];
    float* out = (float*)d_out;

    bf16 *Qh, *Ql, *Kh, *Kl, *Vh, *Vl, *Ah, *Al, *Bh, *Bl;
    bf16 *Wqh, *Wql, *Wkh, *Wkl, *Wvh, *Wvl, *Woh, *Wol;
    cudaGetSymbolAddress((void**)&Qh, g_Qh);  cudaGetSymbolAddress((void**)&Ql, g_Ql);
    cudaGetSymbolAddress((void**)&Kh, g_Kh);  cudaGetSymbolAddress((void**)&Kl, g_Kl);
    cudaGetSymbolAddress((void**)&Vh, g_Vh);  cudaGetSymbolAddress((void**)&Vl, g_Vl);
    cudaGetSymbolAddress((void**)&Ah, g_Ah);  cudaGetSymbolAddress((void**)&Al, g_Al);
    cudaGetSymbolAddress((void**)&Bh, g_Bh);  cudaGetSymbolAddress((void**)&Bl, g_Bl);
    cudaGetSymbolAddress((void**)&Wqh, g_Wqh); cudaGetSymbolAddress((void**)&Wql, g_Wql);
    cudaGetSymbolAddress((void**)&Wkh, g_Wkh); cudaGetSymbolAddress((void**)&Wkl, g_Wkl);
    cudaGetSymbolAddress((void**)&Wvh, g_Wvh); cudaGetSymbolAddress((void**)&Wvl, g_Wvl);
    cudaGetSymbolAddress((void**)&Woh, g_Woh); cudaGetSymbolAddress((void**)&Wol, g_Wol);

    cudaFuncSetAttribute(attn_mma,
                         cudaFuncAttributeMaxDynamicSharedMemorySize, A_SMEM);
    cudaFuncSetAttribute(gemm_mma,
                         cudaFuncAttributeMaxDynamicSharedMemorySize, 4 * GSTG);

    const float qscale = 0.125f * 1.4426950408889634f;

    // all splits (x1, x2, Wq, Wk, Wv, Wo) in one launch
    {
        SArgs sa;
        sa.s[0] = x1; sa.h[0] = Ah;  sa.l[0] = Al;
        sa.s[1] = x2; sa.h[1] = Bh;  sa.l[1] = Bl;
        sa.s[2] = Wq; sa.h[2] = Wqh; sa.l[2] = Wql;
        sa.s[3] = Wk; sa.h[3] = Wkh; sa.l[3] = Wkl;
        sa.s[4] = Wv; sa.h[4] = Wvh; sa.l[4] = Wvl;
        sa.s[5] = Wo; sa.h[5] = Woh; sa.l[5] = Wol;
        convS_kernel<<<8192 + 4 * 1024, 256>>>(sa);
    }

    // fused QKV projections
    {
        GArgs ga;
        ga.Ah[0] = Ah; ga.Al[0] = Al; ga.Wh[0] = Wqh; ga.Wl[0] = Wql;
        ga.bias[0] = bq; ga.oh[0] = Qh; ga.ol[0] = Ql; ga.of[0] = 0; ga.scale[0] = qscale;
        ga.Ah[1] = Bh; ga.Al[1] = Bl; ga.Wh[1] = Wkh; ga.Wl[1] = Wkl;
        ga.bias[1] = bk; ga.oh[1] = Kh; ga.ol[1] = Kl; ga.of[1] = 0; ga.scale[1] = 1.0f;
        ga.Ah[2] = Bh; ga.Al[2] = Bl; ga.Wh[2] = Wvh; ga.Wl[2] = Wvl;
        ga.bias[2] = bv; ga.oh[2] = Vh; ga.ol[2] = Vl; ga.of[2] = 0; ga.scale[2] = 1.0f;
        gemm_mma<<<dim3(DM/128, ROWS/64, 3), 128, 4 * GSTG>>>(ga);
    }

    // attention -> ctx split (overwrites Ah/Al)
    attn_mma<<<dim3(SQL/64, BH), 128, A_SMEM>>>(Qh, Ql, Kh, Kl, Vh, Vl, Ah, Al);

    // out = ctx @ Wo + bo (fp32)
    {
        GArgs ga;
        ga.Ah[0] = Ah; ga.Al[0] = Al; ga.Wh[0] = Woh; ga.Wl[0] = Wol;
        ga.bias[0] = bo; ga.oh[0] = 0; ga.ol[0] = 0; ga.of[0] = out; ga.scale[0] = 1.0f;
        gemm_mma<<<dim3(DM/128, ROWS/64, 1), 128, 4 * GSTG>>>(ga);
    }
}

// round 15
// speedup vs baseline: 1.0559x; 1.0559x over previous
#include <cuda_runtime.h>
#include <cuda_bf16.h>
#include <math.h>
#include <stdint.h>

#define BB   2
#define SQL  2048
#define DM   1024
#define NH   16
#define DH   64
#define BH   32
#define ROWS 4096

typedef __nv_bfloat16 bf16;

// ---------------- scratch (__device__ globals) -----------------------------
__device__ bf16 g_Qh[BH * SQL * DH];
__device__ bf16 g_Ql[BH * SQL * DH];
__device__ bf16 g_Kh[BH * SQL * DH];
__device__ bf16 g_Kl[BH * SQL * DH];
__device__ bf16 g_Vh[BH * SQL * DH];
__device__ bf16 g_Vl[BH * SQL * DH];
__device__ bf16 g_Ah[ROWS * DM];   // x1 split; later ctx split
__device__ bf16 g_Al[ROWS * DM];
__device__ bf16 g_Bh[ROWS * DM];   // x2 split
__device__ bf16 g_Bl[ROWS * DM];
__device__ bf16 g_Wqh[DM * DM], g_Wql[DM * DM];   // untransposed [k][n]
__device__ bf16 g_Wkh[DM * DM], g_Wkl[DM * DM];
__device__ bf16 g_Wvh[DM * DM], g_Wvl[DM * DM];
__device__ bf16 g_Woh[DM * DM], g_Wol[DM * DM];

// ---------------- helpers --------------------------------------------------
__device__ __forceinline__ uint32_t smem_to_u32(const void* p) {
    uint32_t a;
    asm("{ .reg .u64 t; cvta.to.shared.u64 t, %1; cvt.u32.u64 %0, t; }"
        : "=r"(a) : "l"(p));
    return a;
}
__device__ __forceinline__ void ldsm4(uint32_t* r, uint32_t a) {
    asm volatile("ldmatrix.sync.aligned.m8n8.x4.shared.b16 {%0,%1,%2,%3}, [%4];"
        : "=r"(r[0]), "=r"(r[1]), "=r"(r[2]), "=r"(r[3]) : "r"(a));
}
__device__ __forceinline__ void ldsm4t(uint32_t* r, uint32_t a) {
    asm volatile("ldmatrix.sync.aligned.m8n8.x4.trans.shared.b16 {%0,%1,%2,%3}, [%4];"
        : "=r"(r[0]), "=r"(r[1]), "=r"(r[2]), "=r"(r[3]) : "r"(a));
}
__device__ __forceinline__ void mma16816(float* c, const uint32_t* a, const uint32_t* b) {
    asm volatile("mma.sync.aligned.m16n8k16.row.col.f32.bf16.bf16.f32 "
        "{%0,%1,%2,%3}, {%4,%5,%6,%7}, {%8,%9}, {%0,%1,%2,%3};"
        : "+f"(c[0]), "+f"(c[1]), "+f"(c[2]), "+f"(c[3])
        : "r"(a[0]), "r"(a[1]), "r"(a[2]), "r"(a[3]), "r"(b[0]), "r"(b[1]));
}
__device__ __forceinline__ void split2(float v0, float v1, uint32_t& hi2, uint32_t& lo2) {
    __nv_bfloat16 b0 = __float2bfloat16_rn(v0), b1 = __float2bfloat16_rn(v1);
    union { __nv_bfloat162 v; uint32_t u; } p;
    p.v.x = b0; p.v.y = b1; hi2 = p.u;
    p.v.x = __float2bfloat16_rn(v0 - __bfloat162float(b0));
    p.v.y = __float2bfloat16_rn(v1 - __bfloat162float(b1));
    lo2 = p.u;
}
__device__ __forceinline__ float ex2(float x) {
    float y; asm("ex2.approx.f32 %0, %1;" : "=f"(y) : "f"(x)); return y;
}
#define CP16(dst, src) \
    asm volatile("cp.async.cg.shared.global [%0], [%1], 16;" :: "r"(dst), "l"(src))
#define CP_COMMIT() asm volatile("cp.async.commit_group;" ::: "memory")
#define CP_WAIT(n)  asm volatile("cp.async.wait_group %0;" :: "n"(n) : "memory")

// ---------------- one split kernel for x1, x2, and the 4 weights -----------
struct SArgs { const float* s[6]; bf16* h[6]; bf16* l[6]; };
__global__ __launch_bounds__(256)
void convS_kernel(SArgs a)
{
    int bi = blockIdx.x, z;
    if (bi < 4096)       { z = 0; }
    else if (bi < 8192)  { z = 1; bi -= 4096; }
    else                 { z = 2 + ((bi - 8192) >> 10); bi = (bi - 8192) & 1023; }
    const float* __restrict__ x = a.s[z];
    bf16* __restrict__ hi = a.h[z];
    bf16* __restrict__ lo = a.l[z];
    int i = bi * 256 + threadIdx.x;
    float4 v = ((const float4*)x)[i];
    uint32_t h0, l0, h1, l1;
    split2(v.x, v.y, h0, l0);
    split2(v.z, v.w, h1, l1);
    ((uint32_t*)hi)[2 * i] = h0; ((uint32_t*)hi)[2 * i + 1] = h1;
    ((uint32_t*)lo)[2 * i] = l0; ((uint32_t*)lo)[2 * i + 1] = l1;
}

// ---------------- split-bf16 GEMM: 64x128 tile, 128 thr, 3 CTA/SM, 2-stage -
// C[m][n] = sum_k (Ah+Al)[m][k] * (Wh+Wl)[k][n]  (W untransposed; B via ldsm4t)
// stage: Ah 64x80B, Al 64x80B, Bh 32x256B, Bl 32x256B = 26624 B; 2 stages.
struct GArgs {
    const bf16* Ah[3]; const bf16* Al[3];
    const bf16* Wh[3]; const bf16* Wl[3];
    const float* bias[3];
    bf16* oh[3]; bf16* ol[3];
    float* of[3];
    float scale[3];
};
#define GSTG   26624
#define G_OFAL 5120
#define G_OFBH 10240
__global__ __launch_bounds__(128, 3)
void gemm_mma(GArgs ar)
{
    extern __shared__ __align__(16) char dsm[];
    const int z = blockIdx.z;
    const bf16* __restrict__ Ah = ar.Ah[z];
    const bf16* __restrict__ Al = ar.Al[z];
    const bf16* __restrict__ Wh = ar.Wh[z];
    const bf16* __restrict__ Wl = ar.Wl[z];
    const float* __restrict__ bias = ar.bias[z];
    const float scale = ar.scale[z];

    const uint32_t sb0 = smem_to_u32(dsm);
    const int t = threadIdx.x, L = t & 31, wid = t >> 5;
    const int wm = wid & 1, wn = wid >> 1;          // 2x2 warp grid
    const int m0 = blockIdx.y * 64, n0 = blockIdx.x * 128;

    auto copy_stage = [&](int st, int k0) {
        const uint32_t base = sb0 + st * GSTG;
#pragma unroll
        for (int i = 0; i < 2; i++) {
            const int u = t + i * 128, r = u >> 2, c = u & 3;
            const uint32_t d = base + r * 80 + c * 16;
            const size_t gi = (size_t)(m0 + r) * DM + k0 + c * 8;
            CP16(d,          Ah + gi);
            CP16(d + G_OFAL, Al + gi);
        }
#pragma unroll
        for (int i = 0; i < 4; i++) {
            const int u = t + i * 128, r = u >> 4, c = u & 15;
            const uint32_t d = base + G_OFBH + r * 256 + (c ^ (r & 7)) * 16;
            const size_t gi = (size_t)(k0 + r) * DM + n0 + c * 8;
            CP16(d,        Wh + gi);
            CP16(d + 8192, Wl + gi);
        }
    };

    float acc[2][8][4];
#pragma unroll
    for (int a = 0; a < 2; a++)
#pragma unroll
        for (int b = 0; b < 8; b++)
#pragma unroll
            for (int c = 0; c < 4; c++) acc[a][b][c] = 0.0f;

    const int a_row_off = ((L >> 3) & 1) * 8 + (L & 7);
    const int a_ch = (L >> 4);
    const int trow = ((L >> 3) & 1) * 8 + (L & 7);   // B trans row pattern
    const int tcb  = (L >> 4);                       // B trans chunk half
    const int sw7  = L & 7;

    copy_stage(0, 0);
    CP_COMMIT();

    for (int kt = 0; kt < 32; kt++) {
        const int cur = kt & 1;
        if (kt < 31) { copy_stage(1 - cur, (kt + 1) * 32); CP_COMMIT(); CP_WAIT(1); }
        else CP_WAIT(0);
        __syncthreads();
        const uint32_t sb = sb0 + cur * GSTG;
#pragma unroll
        for (int ks = 0; ks < 2; ks++) {
            uint32_t aH[2][4], aL[2][4];
            const int ach = (2 * ks + a_ch) * 16;
#pragma unroll
            for (int mt = 0; mt < 2; mt++) {
                const uint32_t ad = sb + (wm * 32 + mt * 16 + a_row_off) * 80 + ach;
                ldsm4(aH[mt], ad);
                ldsm4(aL[mt], ad + G_OFAL);
            }
            const int krow = ks * 16 + trow;
#pragma unroll
            for (int ns = 0; ns < 4; ns++) {
                uint32_t bTh[4], bTl[4];
                const int ch = 2 * (wn * 4 + ns) + tcb;
                const uint32_t bd = sb + G_OFBH + krow * 256 + ((ch ^ sw7) << 4);
                ldsm4t(bTh, bd);
                ldsm4t(bTl, bd + 8192);
#pragma unroll
                for (int mt = 0; mt < 2; mt++) {
                    mma16816(acc[mt][2 * ns],     aH[mt], &bTh[0]);
                    mma16816(acc[mt][2 * ns],     aH[mt], &bTl[0]);
                    mma16816(acc[mt][2 * ns],     aL[mt], &bTh[0]);
                    mma16816(acc[mt][2 * ns + 1], aH[mt], &bTh[2]);
                    mma16816(acc[mt][2 * ns + 1], aH[mt], &bTl[2]);
                    mma16816(acc[mt][2 * ns + 1], aL[mt], &bTh[2]);
                }
            }
        }
        __syncthreads();
    }

    bf16* __restrict__ outH = ar.oh[z];
    bf16* __restrict__ outL = ar.ol[z];
    float* __restrict__ outF = ar.of[z];
    const int g = L >> 2, tg = L & 3;
#pragma unroll
    for (int mt = 0; mt < 2; mt++) {
#pragma unroll
        for (int nt = 0; nt < 8; nt++) {
            const int mrow = m0 + wm * 32 + mt * 16 + g;
            const int ncol = n0 + wn * 64 + nt * 8 + 2 * tg;
            const float b0v = bias[ncol], b1v = bias[ncol + 1];
            const float v00 = (acc[mt][nt][0] + b0v) * scale;
            const float v01 = (acc[mt][nt][1] + b1v) * scale;
            const float v10 = (acc[mt][nt][2] + b0v) * scale;
            const float v11 = (acc[mt][nt][3] + b1v) * scale;
            if (outF) {
                *(float2*)(outF + (size_t)mrow * DM + ncol) = make_float2(v00, v01);
                *(float2*)(outF + (size_t)(mrow + 8) * DM + ncol) = make_float2(v10, v11);
            } else {
                const int b_ = mrow >> 11, s_ = mrow & 2047;
                const int h_ = ncol >> 6, d_ = ncol & 63;
                const size_t oi = ((size_t)(b_ * NH + h_) * SQL + s_) * DH + d_;
                uint32_t h2, l2;
                split2(v00, v01, h2, l2);
                *(uint32_t*)(outH + oi) = h2;
                *(uint32_t*)(outL + oi) = l2;
                split2(v10, v11, h2, l2);
                *(uint32_t*)(outH + oi + 8 * DH) = h2;
                *(uint32_t*)(outL + oi + 8 * DH) = l2;
            }
        }
    }
}

// ---------------- flash attention (unchanged: 245us, tensor 69%) -----------
#define A_SMEM  81920
#define ASTG_B  16384
#define ASTG_S  32768
__global__ __launch_bounds__(128, 2)
void attn_mma(const bf16* __restrict__ Qh, const bf16* __restrict__ Ql,
              const bf16* __restrict__ Kh, const bf16* __restrict__ Kl,
              const bf16* __restrict__ Vh, const bf16* __restrict__ Vl,
              bf16* __restrict__ Ch, bf16* __restrict__ Cl)
{
    extern __shared__ __align__(16) char sm_[];
    const uint32_t sb = smem_to_u32(sm_);
    const int t = threadIdx.x, L = t & 31, wid = t >> 5;
    const int bh = blockIdx.y, q0 = blockIdx.x * 64;
    const int g = L >> 2, tg = L & 3;

    const int a_row = wid * 16 + ((L >> 3) & 1) * 8 + (L & 7);
    const int a_cb  = (L >> 4);
    const int k_row_off = ((L >> 4) & 1) * 8 + (L & 7);
    const int k_cb  = ((L >> 3) & 1);
    const int v_row_off = ((L >> 3) & 1) * 8 + (L & 7);
    const int v_cb  = (L >> 4);
    const int sw    = L & 7;

    auto copy_kv = [&](int st, int kb) {
        const uint32_t base = sb + ASTG_B + st * ASTG_S;
        const size_t goff = ((size_t)bh * SQL + kb * 64) * DH;
        const char* kh = (const char*)(Kh + goff);
        const char* kl = (const char*)(Kl + goff);
        const char* vh = (const char*)(Vh + goff);
        const char* vl = (const char*)(Vl + goff);
#pragma unroll
        for (int i = 0; i < 4; i++) {
            const int u = t + i * 128, r = u >> 3, c = u & 7;
            const uint32_t so = r * 128 + ((c ^ (r & 7)) << 4);
            const int go = r * 128 + c * 16;
            CP16(base + so,         kh + go);
            CP16(base + 8192 + so,  kl + go);
            CP16(base + 16384 + so, vh + go);
            CP16(base + 24576 + so, vl + go);
        }
    };

    copy_kv(0, 0);
    {
        const char* qh = (const char*)(Qh + ((size_t)bh * SQL + q0) * DH);
        const char* ql = (const char*)(Ql + ((size_t)bh * SQL + q0) * DH);
#pragma unroll
        for (int i = 0; i < 4; i++) {
            const int u = t + i * 128, r = u >> 3, c = u & 7;
            const uint32_t so = r * 128 + ((c ^ (r & 7)) << 4);
            const int go = r * 128 + c * 16;
            CP16(sb + so,        qh + go);
            CP16(sb + 8192 + so, ql + go);
        }
    }
    CP_COMMIT();
    CP_WAIT(0);
    __syncthreads();

    uint32_t qH[4][4], qL[4][4];
#pragma unroll
    for (int ks = 0; ks < 4; ks++) {
        const uint32_t qa = sb + a_row * 128 + (((2 * ks + a_cb) ^ sw) << 4);
        ldsm4(qH[ks], qa);
        ldsm4(qL[ks], qa + 8192);
    }

    float oacc[8][4];
#pragma unroll
    for (int a = 0; a < 8; a++)
#pragma unroll
        for (int b = 0; b < 4; b++) oacc[a][b] = 0.0f;
    float m0r = -1e30f, m1r = -1e30f, l0r = 0.0f, l1r = 0.0f;

    for (int kb = 0; kb < 32; kb++) {
        const int cur = kb & 1;
        if (kb < 31) { copy_kv(1 - cur, kb + 1); CP_COMMIT(); CP_WAIT(1); }
        else CP_WAIT(0);
        __syncthreads();
        const uint32_t kbase = sb + ASTG_B + cur * ASTG_S;

        float sacc[8][4];
#pragma unroll
        for (int j = 0; j < 8; j++)
#pragma unroll
            for (int c = 0; c < 4; c++) sacc[j][c] = 0.0f;

#pragma unroll
        for (int ks = 0; ks < 4; ks++) {
#pragma unroll
            for (int jp = 0; jp < 4; jp++) {
                uint32_t kh4[4], kl4[4];
                const int krow = jp * 16 + k_row_off;
                const uint32_t ka = kbase + krow * 128 + (((2 * ks + k_cb) ^ sw) << 4);
                ldsm4(kh4, ka);
                ldsm4(kl4, ka + 8192);
                mma16816(sacc[2 * jp],     qH[ks], &kh4[0]);
                mma16816(sacc[2 * jp],     qH[ks], &kl4[0]);
                mma16816(sacc[2 * jp],     qL[ks], &kh4[0]);
                mma16816(sacc[2 * jp + 1], qH[ks], &kh4[2]);
                mma16816(sacc[2 * jp + 1], qH[ks], &kl4[2]);
                mma16816(sacc[2 * jp + 1], qL[ks], &kh4[2]);
            }
        }

        float rx0 = -1e30f, rx1 = -1e30f;
#pragma unroll
        for (int j = 0; j < 8; j++) {
            rx0 = fmaxf(rx0, fmaxf(sacc[j][0], sacc[j][1]));
            rx1 = fmaxf(rx1, fmaxf(sacc[j][2], sacc[j][3]));
        }
        rx0 = fmaxf(rx0, __shfl_xor_sync(0xffffffffu, rx0, 1));
        rx0 = fmaxf(rx0, __shfl_xor_sync(0xffffffffu, rx0, 2));
        rx1 = fmaxf(rx1, __shfl_xor_sync(0xffffffffu, rx1, 1));
        rx1 = fmaxf(rx1, __shfl_xor_sync(0xffffffffu, rx1, 2));
        const float mn0 = fmaxf(m0r, rx0), mn1 = fmaxf(m1r, rx1);
        const float al0 = ex2(m0r - mn0), al1 = ex2(m1r - mn1);
        m0r = mn0; m1r = mn1;

        float rs0 = 0.0f, rs1 = 0.0f;
#pragma unroll
        for (int j = 0; j < 8; j++) {
            const float p0 = ex2(sacc[j][0] - mn0);
            const float p1 = ex2(sacc[j][1] - mn0);
            const float p2 = ex2(sacc[j][2] - mn1);
            const float p3 = ex2(sacc[j][3] - mn1);
            sacc[j][0] = p0; sacc[j][1] = p1; sacc[j][2] = p2; sacc[j][3] = p3;
            rs0 += p0 + p1; rs1 += p2 + p3;
        }
        rs0 += __shfl_xor_sync(0xffffffffu, rs0, 1);
        rs0 += __shfl_xor_sync(0xffffffffu, rs0, 2);
        rs1 += __shfl_xor_sync(0xffffffffu, rs1, 1);
        rs1 += __shfl_xor_sync(0xffffffffu, rs1, 2);
        l0r = l0r * al0 + rs0;
        l1r = l1r * al1 + rs1;
#pragma unroll
        for (int jd = 0; jd < 8; jd++) {
            oacc[jd][0] *= al0; oacc[jd][1] *= al0;
            oacc[jd][2] *= al1; oacc[jd][3] *= al1;
        }

#pragma unroll
        for (int ks2 = 0; ks2 < 4; ks2++) {
            uint32_t ph[4], pl[4];
            split2(sacc[2 * ks2][0],     sacc[2 * ks2][1],     ph[0], pl[0]);
            split2(sacc[2 * ks2][2],     sacc[2 * ks2][3],     ph[1], pl[1]);
            split2(sacc[2 * ks2 + 1][0], sacc[2 * ks2 + 1][1], ph[2], pl[2]);
            split2(sacc[2 * ks2 + 1][2], sacc[2 * ks2 + 1][3], ph[3], pl[3]);
#pragma unroll
            for (int jdp = 0; jdp < 4; jdp++) {
                uint32_t vh4[4], vl4[4];
                const int vrow = ks2 * 16 + v_row_off;
                const uint32_t va = kbase + 16384 + vrow * 128
                                  + (((2 * jdp + v_cb) ^ sw) << 4);
                ldsm4t(vh4, va);
                ldsm4t(vl4, va + 8192);
                mma16816(oacc[2 * jdp],     ph, &vh4[0]);
                mma16816(oacc[2 * jdp],     ph, &vl4[0]);
                mma16816(oacc[2 * jdp],     pl, &vh4[0]);
                mma16816(oacc[2 * jdp + 1], ph, &vh4[2]);
                mma16816(oacc[2 * jdp + 1], ph, &vl4[2]);
                mma16816(oacc[2 * jdp + 1], pl, &vh4[2]);
            }
        }
        __syncthreads();
    }

    const float inv0 = 1.0f / l0r, inv1 = 1.0f / l1r;
    const int b_ = bh >> 4, h_ = bh & 15;
    const int q_g = q0 + wid * 16 + g;
    const size_t base0 = ((size_t)(b_ * SQL + q_g)) * DM + h_ * DH;
    const size_t base1 = base0 + (size_t)8 * DM;
#pragma unroll
    for (int jd = 0; jd < 8; jd++) {
        const int dcol = jd * 8 + 2 * tg;
        uint32_t h2, l2;
        split2(oacc[jd][0] * inv0, oacc[jd][1] * inv0, h2, l2);
        *(uint32_t*)(Ch + base0 + dcol) = h2;
        *(uint32_t*)(Cl + base0 + dcol) = l2;
        split2(oacc[jd][2] * inv1, oacc[jd][3] * inv1, h2, l2);
        *(uint32_t*)(Ch + base1 + dcol) = h2;
        *(uint32_t*)(Cl + base1 + dcol) = l2;
    }
}

// ---------------------------------------------------------------------------
extern "C" void kernel_launch(void* const* d_in, const int* in_sizes, int n_in,
                              void* d_out, int out_size)
{
    const float* x1 = (const float*)d_in[0];
    const float* x2 = (const float*)d_in[1];
    const float* Wq = (const float*)d_in[2];
    const float* bq = (const float*)d_in[3];
    const float* Wk = (const float*)d_in[4];
    const float* bk = (const float*)d_in[5];
    const float* Wv = (const float*)d_in[6];
    const float* bv = (const float*)d_in[7];
    const float* Wo = (const float*)d_in[8];
    const float* bo = (const float*)d_in[9];
    float* out = (float*)d_out;

    bf16 *Qh, *Ql, *Kh, *Kl, *Vh, *Vl, *Ah, *Al, *Bh, *Bl;
    bf16 *Wqh, *Wql, *Wkh, *Wkl, *Wvh, *Wvl, *Woh, *Wol;
    cudaGetSymbolAddress((void**)&Qh, g_Qh);  cudaGetSymbolAddress((void**)&Ql, g_Ql);
    cudaGetSymbolAddress((void**)&Kh, g_Kh);  cudaGetSymbolAddress((void**)&Kl, g_Kl);
    cudaGetSymbolAddress((void**)&Vh, g_Vh);  cudaGetSymbolAddress((void**)&Vl, g_Vl);
    cudaGetSymbolAddress((void**)&Ah, g_Ah);  cudaGetSymbolAddress((void**)&Al, g_Al);
    cudaGetSymbolAddress((void**)&Bh, g_Bh);  cudaGetSymbolAddress((void**)&Bl, g_Bl);
    cudaGetSymbolAddress((void**)&Wqh, g_Wqh); cudaGetSymbolAddress((void**)&Wql, g_Wql);
    cudaGetSymbolAddress((void**)&Wkh, g_Wkh); cudaGetSymbolAddress((void**)&Wkl, g_Wkl);
    cudaGetSymbolAddress((void**)&Wvh, g_Wvh); cudaGetSymbolAddress((void**)&Wvl, g_Wvl);
    cudaGetSymbolAddress((void**)&Woh, g_Woh); cudaGetSymbolAddress((void**)&Wol, g_Wol);

    cudaFuncSetAttribute(attn_mma,
                         cudaFuncAttributeMaxDynamicSharedMemorySize, A_SMEM);
    cudaFuncSetAttribute(gemm_mma,
                         cudaFuncAttributeMaxDynamicSharedMemorySize, 2 * GSTG);

    const float qscale = 0.125f * 1.4426950408889634f;

    // all splits (x1, x2, Wq, Wk, Wv, Wo) in one launch
    {
        SArgs sa;
        sa.s[0] = x1; sa.h[0] = Ah;  sa.l[0] = Al;
        sa.s[1] = x2; sa.h[1] = Bh;  sa.l[1] = Bl;
        sa.s[2] = Wq; sa.h[2] = Wqh; sa.l[2] = Wql;
        sa.s[3] = Wk; sa.h[3] = Wkh; sa.l[3] = Wkl;
        sa.s[4] = Wv; sa.h[4] = Wvh; sa.l[4] = Wvl;
        sa.s[5] = Wo; sa.h[5] = Woh; sa.l[5] = Wol;
        convS_kernel<<<8192 + 4 * 1024, 256>>>(sa);
    }

    // fused QKV projections
    {
        GArgs ga;
        ga.Ah[0] = Ah; ga.Al[0] = Al; ga.Wh[0] = Wqh; ga.Wl[0] = Wql;
        ga.bias[0] = bq; ga.oh[0] = Qh; ga.ol[0] = Ql; ga.of[0] = 0; ga.scale[0] = qscale;
        ga.Ah[1] = Bh; ga.Al[1] = Bl; ga.Wh[1] = Wkh; ga.Wl[1] = Wkl;
        ga.bias[1] = bk; ga.oh[1] = Kh; ga.ol[1] = Kl; ga.of[1] = 0; ga.scale[1] = 1.0f;
        ga.Ah[2] = Bh; ga.Al[2] = Bl; ga.Wh[2] = Wvh; ga.Wl[2] = Wvl;
        ga.bias[2] = bv; ga.oh[2] = Vh; ga.ol[2] = Vl; ga.of[2] = 0; ga.scale[2] = 1.0f;
        gemm_mma<<<dim3(DM/128, ROWS/64, 3), 128, 2 * GSTG>>>(ga);
    }

    // attention -> ctx split (overwrites Ah/Al)
    attn_mma<<<dim3(SQL/64, BH), 128, A_SMEM>>>(Qh, Ql, Kh, Kl, Vh, Vl, Ah, Al);

    // out = ctx @ Wo + bo (fp32)
    {
        GArgs ga;
        ga.Ah[0] = Ah; ga.Al[0] = Al; ga.Wh[0] = Woh; ga.Wl[0] = Wol;
        ga.bias[0] = bo; ga.oh[0] = 0; ga.ol[0] = 0; ga.of[0] = out; ga.scale[0] = 1.0f;
        gemm_mma<<<dim3(DM/128, ROWS/64, 1), 128, 2 * GSTG>>>(ga);
    }
}